// round 7
// baseline (speedup 1.0000x reference)
#include <cuda_runtime.h>
#include <cuda_fp16.h>
#include <math.h>

// Problem constants
#define BB   16      // batch
#define CI   2048    // input capsules
#define NI   16      // input capsule dim
#define CJ   64      // output capsules
#define NJ   32      // output capsule dim
#define JM   2048    // CJ*NJ
#define K1_CHUNK 2   // i's per prefix chunk (acc reset period)
#define K1_IBLK  4   // i's per K1 block
#define K1_NBLK  (CI / K1_IBLK)           // 512
#define RT_ICHUNK 32                      // i's per routing block (mult of 4)
#define RT_NIB    (CI / RT_ICHUNK)        // 64
#define AL2E 11.541560327111707f          // 8 * log2(e)

typedef unsigned long long ull;

// g_Uh: chunk-local PREFIX sums of u over i (chunk=2), fp16, layout [i][b][jm]
static __device__ __half g_Uh[(size_t)CI * BB * JM];  // 134 MB
static __device__ float  g_s[BB * JM];                // s accumulator (BSS zero)
static __device__ float  g_v[BB * JM];                // squashed v
static __device__ float  g_bl[(size_t)BB * CI * CJ];  // routing logits [b][i][j]

// ---- packed fp32 pair helpers (fma.rn.f32x2, sm_100+) ----------------------
__device__ __forceinline__ void fma2(ull& d, ull a, ull b) {
    asm("fma.rn.f32x2 %0, %1, %2, %0;" : "+l"(d) : "l"(a), "l"(b));
}
__device__ __forceinline__ ull pack2(float x, float y) {
    ull r; asm("mov.b64 %0, {%1, %2};" : "=l"(r) : "f"(x), "f"(y)); return r;
}
__device__ __forceinline__ float2 unpack2(ull v) {
    float2 r; asm("mov.b64 {%0, %1}, %2;" : "=f"(r.x), "=f"(r.y) : "l"(v)); return r;
}

// ---------------------------------------------------------------------------
// K1: u[b,i,jm] = sum_n x[b,i,n] * w[i,n,jm]; writes 2-i chunk prefix sums as
// fp16. 512 blocks x 512 threads; thread owns jm quad [4t,4t+4).
// R4 structure (grouped W loads, no cross-group lookahead) + single X preload.
// ---------------------------------------------------------------------------
__global__ void __launch_bounds__(512) k_u_prefix(const float* __restrict__ X,
                                                  const float* __restrict__ W)
{
    __shared__ __align__(16) float x_s[K1_IBLK][NI][BB];
    const int t  = threadIdx.x;
    const int i0 = blockIdx.x * K1_IBLK;

    // preload X for all 4 i's (1024 floats), single sync
#pragma unroll
    for (int rep = 0; rep < 2; rep++) {
        const int idx = t + rep * 512;
        const int ci = idx >> 8, rem = idx & 255, n = rem >> 4, b = rem & 15;
        x_s[ci][n][b] = X[((size_t)b * CI + (i0 + ci)) * NI + n];
    }
    __syncthreads();

    ull acc2[8][4];   // [b-pair][q]: packed (acc[2bp][q], acc[2bp+1][q])

    const float4* W4 = (const float4*)W;
    uint2*        U2 = (uint2*)g_Uh;              // 4 halfs per uint2

    for (int ci = 0; ci < K1_IBLK; ci++) {
        const int i = i0 + ci;
        if ((ci & (K1_CHUNK - 1)) == 0) {
#pragma unroll
            for (int bp = 0; bp < 8; bp++)
#pragma unroll
                for (int q = 0; q < 4; q++) acc2[bp][q] = 0ull;
        }

#pragma unroll
        for (int ng = 0; ng < 4; ng++) {
            float4 wst[4];
#pragma unroll
            for (int k = 0; k < 4; k++)
                wst[k] = W4[(size_t)(i * NI + ng * 4 + k) * (JM / 4) + t];
#pragma unroll
            for (int k = 0; k < 4; k++) {
                const int n = ng * 4 + k;
                const ull* xs8 = (const ull*)&x_s[ci][n][0];   // batch pairs
                const float4 wv = wst[k];
                const ull wd0 = pack2(wv.x, wv.x);
                const ull wd1 = pack2(wv.y, wv.y);
                const ull wd2 = pack2(wv.z, wv.z);
                const ull wd3 = pack2(wv.w, wv.w);
#pragma unroll
                for (int bp = 0; bp < 8; bp++) {
                    const ull xp = xs8[bp];
                    fma2(acc2[bp][0], xp, wd0);
                    fma2(acc2[bp][1], xp, wd1);
                    fma2(acc2[bp][2], xp, wd2);
                    fma2(acc2[bp][3], xp, wd3);
                }
            }
        }

        // store fp16 prefix row for this i
#pragma unroll
        for (int bp = 0; bp < 8; bp++) {
            const float2 a0 = unpack2(acc2[bp][0]);
            const float2 a1 = unpack2(acc2[bp][1]);
            const float2 a2 = unpack2(acc2[bp][2]);
            const float2 a3 = unpack2(acc2[bp][3]);
            __half2 lo0 = __floats2half2_rn(a0.x, a1.x);
            __half2 lo1 = __floats2half2_rn(a2.x, a3.x);
            __half2 hi0 = __floats2half2_rn(a0.y, a1.y);
            __half2 hi1 = __floats2half2_rn(a2.y, a3.y);
            uint2 vlo, vhi;
            vlo.x = *(unsigned*)&lo0; vlo.y = *(unsigned*)&lo1;
            vhi.x = *(unsigned*)&hi0; vhi.y = *(unsigned*)&hi1;
            U2[(size_t)(i * BB + 2*bp)     * (JM/4) + t] = vlo;
            U2[(size_t)(i * BB + 2*bp + 1) * (JM/4) + t] = vhi;
        }
    }
}

// ---------------------------------------------------------------------------
// K2: s0[b,jm] = sum over odd-i prefix rows (chunk=2). g_s zero beforehand.
// ---------------------------------------------------------------------------
__global__ void __launch_bounds__(256) k_s0_reduce()
{
    const int bid = blockIdx.x;
    const int cq  = bid & 3;
    const int jmc = (bid >> 2) & 7;
    const int b   = bid >> 5;
    const int jm  = jmc * 256 + threadIdx.x;
    const int c0  = cq * (CI / 2 / 4);     // 256 odd rows per quarter

    float a = 0.0f;
#pragma unroll 8
    for (int c = 0; c < CI / 2 / 4; c++) {
        const int i = (c0 + c) * 2 + 1;    // odd i = chunk-last row
        a += __half2float(g_Uh[(size_t)(i * BB + b) * JM + jm]);
    }
    atomicAdd(&g_s[b * JM + jm], a);
}

// ---- fp16 row helpers for routing -----------------------------------------
__device__ __forceinline__ void cvt_row(const uint4& p, float* u) {
    float2 f;
    f = __half22float2(*(__half2*)&p.x); u[0]=f.x; u[1]=f.y;
    f = __half22float2(*(__half2*)&p.y); u[2]=f.x; u[3]=f.y;
    f = __half22float2(*(__half2*)&p.z); u[4]=f.x; u[5]=f.y;
    f = __half22float2(*(__half2*)&p.w); u[6]=f.x; u[7]=f.y;
}

// ---------------------------------------------------------------------------
// Routing pass (pass=1: writes b1; pass=2: reads b1).
// Grid (64, 16) x 256 threads; thread owns jm [8t,8t+8), j = t>>2.
// 4 rows (2 prefix chunks) per barrier phase -> 8 barriers/block. Rows held
// as raw uint4 fp16 (16 regs); converted on the fly for dot and accumulate.
// ---------------------------------------------------------------------------
__global__ void __launch_bounds__(256, 3) k_route(int pass)
{
    __shared__ float red_sum[2][4][8];   // [buf][row][warp]

    const int t  = threadIdx.x;
    const int l  = t & 31;
    const int wp = t >> 5;
    const int gl = t & 3;
    const int b  = blockIdx.y;
    const int i0 = blockIdx.x * RT_ICHUNK;
    const int j  = t >> 2;

    float v_r[8];
    {
        const float4* gv4 = (const float4*)g_v;
        float4 va = gv4[b * (JM/4) + 2*t];
        float4 vb = gv4[b * (JM/4) + 2*t + 1];
        v_r[0]=va.x; v_r[1]=va.y; v_r[2]=va.z; v_r[3]=va.w;
        v_r[4]=vb.x; v_r[5]=vb.y; v_r[6]=vb.z; v_r[7]=vb.w;
    }

    float s_loc[8];
#pragma unroll
    for (int k = 0; k < 8; k++) s_loc[k] = 0.0f;

    const uint4* U4 = (const uint4*)g_Uh;            // 8 halfs per uint4
    const size_t rstride = (size_t)BB * (JM/8);      // uint4 per i step
    const size_t base    = ((size_t)i0 * BB + b) * (JM/8) + t;
    float* BL = g_bl + ((size_t)b * CI + i0) * CJ + j;

    uint4 R[4];
#pragma unroll
    for (int r = 0; r < 4; r++)
        R[r] = U4[base + (size_t)r * rstride];

    for (int bi = 0; bi < RT_ICHUNK / 4; bi++) {
        // prefetch next 4 rows
        uint4 N[4];
        if (bi < RT_ICHUNK / 4 - 1) {
            const size_t nb = base + (size_t)(4*bi + 4) * rstride;
#pragma unroll
            for (int r = 0; r < 4; r++) N[r] = U4[nb + (size_t)r * rstride];
        }

        float blp[4];
        if (pass == 2) {
#pragma unroll
            for (int r = 0; r < 4; r++)
                blp[r] = BL[(size_t)(4*bi + r) * CJ];
        }

        // dots: convert chunks transiently (u regs reused across chunks)
        float d[4];
        {
            float uA[8], uB[8];
#pragma unroll
            for (int c = 0; c < 2; c++) {
                cvt_row(R[2*c], uA); cvt_row(R[2*c + 1], uB);
                float dA = 0.0f, dB = 0.0f;
#pragma unroll
                for (int k = 0; k < 8; k++) {
                    uB[k] -= uA[k];
                    dA += v_r[k] * uA[k];
                    dB += v_r[k] * uB[k];
                }
                d[2*c] = dA; d[2*c + 1] = dB;
            }
        }
#pragma unroll
        for (int r = 0; r < 4; r++)
            d[r] += __shfl_xor_sync(0xffffffffu, d[r], 1);
#pragma unroll
        for (int r = 0; r < 4; r++)
            d[r] += __shfl_xor_sync(0xffffffffu, d[r], 2);

        if (pass == 2) {
#pragma unroll
            for (int r = 0; r < 4; r++) d[r] += blp[r];
        } else if (gl == 0) {
#pragma unroll
            for (int r = 0; r < 4; r++)
                BL[(size_t)(4*bi + r) * CJ] = d[r];
        }

        // softmax over j, alpha=8, no max shift (logits bounded; fp32-safe)
        float e[4], es[4];
#pragma unroll
        for (int r = 0; r < 4; r++) { e[r] = exp2f(d[r] * AL2E); es[r] = e[r]; }
#pragma unroll
        for (int o = 4; o <= 16; o <<= 1) {
#pragma unroll
            for (int r = 0; r < 4; r++)
                es[r] += __shfl_xor_sync(0xffffffffu, es[r], o);
        }
        const int pb = bi & 1;
        if (l == 0) {
#pragma unroll
            for (int r = 0; r < 4; r++) red_sum[pb][r][wp] = es[r];
        }
        __syncthreads();

        const float4* rs = (const float4*)&red_sum[pb][0][0];
        float cc[4];
#pragma unroll
        for (int r = 0; r < 4; r++) {
            const float4 a = rs[2*r], c4 = rs[2*r + 1];
            const float tot = ((a.x + a.y) + (a.z + a.w)) +
                              ((c4.x + c4.y) + (c4.z + c4.w));
            cc[r] = __fdividef(64.0f * e[r], tot);
        }

        // accumulate (re-convert from retained uint4 regs)
        {
            float uA[8], uB[8];
#pragma unroll
            for (int c = 0; c < 2; c++) {
                cvt_row(R[2*c], uA); cvt_row(R[2*c + 1], uB);
                const float ca = cc[2*c], cb = cc[2*c + 1];
#pragma unroll
                for (int k = 0; k < 8; k++) {
                    uB[k] -= uA[k];
                    s_loc[k] += ca * uA[k] + cb * uB[k];
                }
            }
        }

#pragma unroll
        for (int r = 0; r < 4; r++) R[r] = N[r];
    }

#pragma unroll
    for (int k = 0; k < 8; k++)
        atomicAdd(&g_s[b * JM + 8*t + k], s_loc[k]);
}

// ---------------------------------------------------------------------------
// Squash: v = (|s|^2/(1+|s|^2)) * s * rsqrt(|s|^2 + eps). Re-zeroes g_s.
// ---------------------------------------------------------------------------
__global__ void __launch_bounds__(512) k_squash(float* dst)
{
    const int t    = threadIdx.x;
    const int gw   = blockIdx.x * 16 + (t >> 5);
    const int lane = t & 31;
    const int b    = gw >> 6;
    const int j    = gw & 63;
    const int idx  = b * JM + j * NJ + lane;

    const float s = g_s[idx];
    float sq = s * s;
#pragma unroll
    for (int o = 16; o > 0; o >>= 1)
        sq += __shfl_xor_sync(0xffffffffu, sq, o);

    const float coef = (sq / (1.0f + sq)) * rsqrtf(sq + 1e-7f);
    float* out = dst ? dst : g_v;
    out[idx] = s * coef;
    g_s[idx] = 0.0f;
}

// ---------------------------------------------------------------------------
extern "C" void kernel_launch(void* const* d_in, const int* in_sizes, int n_in,
                              void* d_out, int out_size)
{
    const float* X = (const float*)d_in[0];
    const float* W = (const float*)d_in[1];
    if (n_in >= 2 && in_sizes[0] > in_sizes[1]) {   // defensive order check
        const float* tmp = X; X = W; W = tmp;
    }
    float* out = (float*)d_out;

    k_u_prefix<<<K1_NBLK, 512>>>(X, W);
    k_s0_reduce<<<512, 256>>>();
    k_squash<<<64, 512>>>(nullptr);                 // v0, zero g_s
    k_route<<<dim3(RT_NIB, BB), 256>>>(1);
    k_squash<<<64, 512>>>(nullptr);                 // v1, zero g_s
    k_route<<<dim3(RT_NIB, BB), 256>>>(2);
    k_squash<<<64, 512>>>(out);                     // v2 -> output, zero g_s
    (void)out_size;
}

// round 8
// speedup vs baseline: 1.4091x; 1.4091x over previous
#include <cuda_runtime.h>
#include <cuda_fp16.h>
#include <math.h>

// Problem constants
#define BB   16      // batch
#define CI   2048    // input capsules
#define NI   16      // input capsule dim
#define CJ   64      // output capsules
#define NJ   32      // output capsule dim
#define JM   2048    // CJ*NJ
#define K1_CHUNK 2   // i's per prefix chunk (acc reset period)
#define K1_IBLK  4   // i's per K1 block
#define RT_ICHUNK 32                      // i's per routing block (even)
#define RT_NIB    (CI / RT_ICHUNK)        // 64
#define AL2E 11.541560327111707f          // 8 * log2(e)

typedef unsigned long long ull;

// g_Uh: chunk-local PREFIX sums of u over i (chunk=2), fp16, layout [i][b][jm]
static __device__ __half g_Uh[(size_t)CI * BB * JM];  // 134 MB
static __device__ float  g_s[BB * JM];                // s accumulator (BSS zero)
static __device__ float  g_v[BB * JM];                // squashed v
static __device__ float  g_bl[(size_t)BB * CI * CJ];  // routing logits [b][i][j]

// ---- packed fp32 pair helpers (fma.rn.f32x2, sm_100+) ----------------------
__device__ __forceinline__ void fma2(ull& d, ull a, ull b) {
    asm("fma.rn.f32x2 %0, %1, %2, %0;" : "+l"(d) : "l"(a), "l"(b));
}
__device__ __forceinline__ ull pack2(float x, float y) {
    ull r; asm("mov.b64 %0, {%1, %2};" : "=l"(r) : "f"(x), "f"(y)); return r;
}
__device__ __forceinline__ float2 unpack2(ull v) {
    float2 r; asm("mov.b64 {%0, %1}, %2;" : "=f"(r.x), "=f"(r.y) : "l"(v)); return r;
}

// ---------------------------------------------------------------------------
// K1: u[b,i,jm] = sum_n x[b,i,n] * w[i,n,jm]; writes 2-i chunk prefix sums as
// fp16.  Grid: (512 i-groups, 2 jm-halves) = 1024 blocks x 256 threads.
// Thread owns jm quad [h*1024 + 4t, +4); same acc layout as before (16 b x 4
// jm packed in 32 ull).  2 blocks/SM + 7 waves -> store tails overlap.
// ---------------------------------------------------------------------------
__global__ void __launch_bounds__(256) k_u_prefix(const float* __restrict__ X,
                                                  const float* __restrict__ W)
{
    __shared__ __align__(16) float x_s[K1_IBLK][NI][BB];
    const int t  = threadIdx.x;
    const int i0 = blockIdx.x * K1_IBLK;
    const int qh = blockIdx.y * 256;          // quad offset of this jm-half

    // preload X for all 4 i's (1024 floats), single sync
#pragma unroll
    for (int rep = 0; rep < 4; rep++) {
        const int idx = t + rep * 256;
        const int ci = idx >> 8, rem = idx & 255, n = rem >> 4, b = rem & 15;
        x_s[ci][n][b] = X[((size_t)b * CI + (i0 + ci)) * NI + n];
    }
    __syncthreads();

    ull acc2[8][4];   // [b-pair][q]: packed (acc[2bp][q], acc[2bp+1][q])

    const float4* W4 = (const float4*)W;
    uint2*        U2 = (uint2*)g_Uh;              // 4 halfs per uint2
    const int     tq = qh + t;                    // this thread's quad index

    for (int ci = 0; ci < K1_IBLK; ci++) {
        const int i = i0 + ci;
        if ((ci & (K1_CHUNK - 1)) == 0) {
#pragma unroll
            for (int bp = 0; bp < 8; bp++)
#pragma unroll
                for (int q = 0; q < 4; q++) acc2[bp][q] = 0ull;
        }

#pragma unroll
        for (int ng = 0; ng < 4; ng++) {
            float4 wst[4];
#pragma unroll
            for (int k = 0; k < 4; k++)
                wst[k] = W4[(size_t)(i * NI + ng * 4 + k) * (JM / 4) + tq];
#pragma unroll
            for (int k = 0; k < 4; k++) {
                const int n = ng * 4 + k;
                const ull* xs8 = (const ull*)&x_s[ci][n][0];   // batch pairs
                const float4 wv = wst[k];
                const ull wd0 = pack2(wv.x, wv.x);
                const ull wd1 = pack2(wv.y, wv.y);
                const ull wd2 = pack2(wv.z, wv.z);
                const ull wd3 = pack2(wv.w, wv.w);
#pragma unroll
                for (int bp = 0; bp < 8; bp++) {
                    const ull xp = xs8[bp];
                    fma2(acc2[bp][0], xp, wd0);
                    fma2(acc2[bp][1], xp, wd1);
                    fma2(acc2[bp][2], xp, wd2);
                    fma2(acc2[bp][3], xp, wd3);
                }
            }
        }

        // store fp16 prefix row for this i
#pragma unroll
        for (int bp = 0; bp < 8; bp++) {
            const float2 a0 = unpack2(acc2[bp][0]);
            const float2 a1 = unpack2(acc2[bp][1]);
            const float2 a2 = unpack2(acc2[bp][2]);
            const float2 a3 = unpack2(acc2[bp][3]);
            __half2 lo0 = __floats2half2_rn(a0.x, a1.x);
            __half2 lo1 = __floats2half2_rn(a2.x, a3.x);
            __half2 hi0 = __floats2half2_rn(a0.y, a1.y);
            __half2 hi1 = __floats2half2_rn(a2.y, a3.y);
            uint2 vlo, vhi;
            vlo.x = *(unsigned*)&lo0; vlo.y = *(unsigned*)&lo1;
            vhi.x = *(unsigned*)&hi0; vhi.y = *(unsigned*)&hi1;
            U2[(size_t)(i * BB + 2*bp)     * (JM/4) + tq] = vlo;
            U2[(size_t)(i * BB + 2*bp + 1) * (JM/4) + tq] = vhi;
        }
    }
}

// ---------------------------------------------------------------------------
// K2: s0[b,jm] = sum over odd-i prefix rows (chunk=2). g_s zero beforehand.
// ---------------------------------------------------------------------------
__global__ void __launch_bounds__(256) k_s0_reduce()
{
    const int bid = blockIdx.x;
    const int cq  = bid & 3;
    const int jmc = (bid >> 2) & 7;
    const int b   = bid >> 5;
    const int jm  = jmc * 256 + threadIdx.x;
    const int c0  = cq * (CI / 2 / 4);     // 256 odd rows per quarter

    float a = 0.0f;
#pragma unroll 8
    for (int c = 0; c < CI / 2 / 4; c++) {
        const int i = (c0 + c) * 2 + 1;    // odd i = chunk-last row
        a += __half2float(g_Uh[(size_t)(i * BB + b) * JM + jm]);
    }
    atomicAdd(&g_s[b * JM + jm], a);
}

// ---- fp16 row helper for routing ------------------------------------------
__device__ __forceinline__ void cvt_row(const uint4& p, float* u) {
    float2 f;
    f = __half22float2(*(__half2*)&p.x); u[0]=f.x; u[1]=f.y;
    f = __half22float2(*(__half2*)&p.y); u[2]=f.x; u[3]=f.y;
    f = __half22float2(*(__half2*)&p.z); u[4]=f.x; u[5]=f.y;
    f = __half22float2(*(__half2*)&p.w); u[6]=f.x; u[7]=f.y;
}

// ---------------------------------------------------------------------------
// Routing pass — EXACT R4 structure (best measured: 51.6us/pass, 63 regs).
// Grid (64, 16) x 256 threads; thread owns jm [8t, 8t+8), j = t>>2.
// 2-row batches == prefix chunk: uA = P0, uB = P1 - P0.
// ---------------------------------------------------------------------------
__global__ void __launch_bounds__(256) k_route(int pass)
{
    __shared__ float red_sum[2][2][8];   // [buf][row][warp]

    const int t  = threadIdx.x;
    const int l  = t & 31;
    const int wp = t >> 5;
    const int gl = t & 3;
    const int b  = blockIdx.y;
    const int i0 = blockIdx.x * RT_ICHUNK;
    const int j  = t >> 2;

    float v_r[8];
    {
        const float4* gv4 = (const float4*)g_v;
        float4 va = gv4[b * (JM/4) + 2*t];
        float4 vb = gv4[b * (JM/4) + 2*t + 1];
        v_r[0]=va.x; v_r[1]=va.y; v_r[2]=va.z; v_r[3]=va.w;
        v_r[4]=vb.x; v_r[5]=vb.y; v_r[6]=vb.z; v_r[7]=vb.w;
    }

    float s_loc[8];
#pragma unroll
    for (int k = 0; k < 8; k++) s_loc[k] = 0.0f;

    const uint4* U4 = (const uint4*)g_Uh;            // 8 halfs per uint4
    const size_t rstride = (size_t)BB * (JM/8);      // uint4 per i step
    const size_t base    = ((size_t)i0 * BB + b) * (JM/8) + t;

    float* BL = g_bl + ((size_t)b * CI + i0) * CJ + j;

    uint4 A = U4[base];
    uint4 B = U4[base + rstride];

    for (int bi = 0; bi < RT_ICHUNK / 2; bi++) {
        // prefetch next chunk
        uint4 C, D;
        if (bi < RT_ICHUNK / 2 - 1) {
            const size_t nb = base + (size_t)(2*bi + 2) * rstride;
            C = U4[nb]; D = U4[nb + rstride];
        }

        float blpA = 0.0f, blpB = 0.0f;
        if (pass == 2) {
            blpA = BL[(size_t)(2*bi)     * CJ];
            blpB = BL[(size_t)(2*bi + 1) * CJ];
        }

        // convert to fp32
        float uA[8], uB[8];
        cvt_row(A, uA); cvt_row(B, uB);
        // reconstruct: uA = u_{2bi}, uB = P1 - P0 = u_{2bi+1}
#pragma unroll
        for (int k = 0; k < 8; k++) uB[k] -= uA[k];

        // agreement dots
        float dA = 0.0f, dB = 0.0f;
#pragma unroll
        for (int k = 0; k < 8; k++) { dA += v_r[k]*uA[k]; dB += v_r[k]*uB[k]; }
        dA += __shfl_xor_sync(0xffffffffu, dA, 1);
        dA += __shfl_xor_sync(0xffffffffu, dA, 2);
        dB += __shfl_xor_sync(0xffffffffu, dB, 1);
        dB += __shfl_xor_sync(0xffffffffu, dB, 2);

        if (pass == 2) { dA += blpA; dB += blpB; }
        else if (gl == 0) {
            BL[(size_t)(2*bi)     * CJ] = dA;
            BL[(size_t)(2*bi + 1) * CJ] = dB;
        }

        // softmax over j, alpha=8, no max shift (logits bounded; fp32-safe)
        const float eA = exp2f(dA * AL2E);
        const float eB = exp2f(dB * AL2E);

        float esA = eA, esB = eB;
#pragma unroll
        for (int o = 4; o <= 16; o <<= 1) {
            esA += __shfl_xor_sync(0xffffffffu, esA, o);
            esB += __shfl_xor_sync(0xffffffffu, esB, o);
        }
        const int pb = bi & 1;
        if (l == 0) { red_sum[pb][0][wp] = esA; red_sum[pb][1][wp] = esB; }
        __syncthreads();

        const float4* rs = (const float4*)&red_sum[pb][0][0];
        float4 r0 = rs[0], r1 = rs[1], r2 = rs[2], r3 = rs[3];
        const float totA = ((r0.x + r0.y) + (r0.z + r0.w)) +
                           ((r1.x + r1.y) + (r1.z + r1.w));
        const float totB = ((r2.x + r2.y) + (r2.z + r2.w)) +
                           ((r3.x + r3.y) + (r3.z + r3.w));

        const float ccA = __fdividef(64.0f * eA, totA);
        const float ccB = __fdividef(64.0f * eB, totB);
#pragma unroll
        for (int k = 0; k < 8; k++) s_loc[k] += ccA * uA[k] + ccB * uB[k];

        A = C; B = D;
    }

#pragma unroll
    for (int k = 0; k < 8; k++)
        atomicAdd(&g_s[b * JM + 8*t + k], s_loc[k]);
}

// ---------------------------------------------------------------------------
// Squash: v = (|s|^2/(1+|s|^2)) * s * rsqrt(|s|^2 + eps). Re-zeroes g_s.
// ---------------------------------------------------------------------------
__global__ void __launch_bounds__(512) k_squash(float* dst)
{
    const int t    = threadIdx.x;
    const int gw   = blockIdx.x * 16 + (t >> 5);
    const int lane = t & 31;
    const int b    = gw >> 6;
    const int j    = gw & 63;
    const int idx  = b * JM + j * NJ + lane;

    const float s = g_s[idx];
    float sq = s * s;
#pragma unroll
    for (int o = 16; o > 0; o >>= 1)
        sq += __shfl_xor_sync(0xffffffffu, sq, o);

    const float coef = (sq / (1.0f + sq)) * rsqrtf(sq + 1e-7f);
    float* out = dst ? dst : g_v;
    out[idx] = s * coef;
    g_s[idx] = 0.0f;
}

// ---------------------------------------------------------------------------
extern "C" void kernel_launch(void* const* d_in, const int* in_sizes, int n_in,
                              void* d_out, int out_size)
{
    const float* X = (const float*)d_in[0];
    const float* W = (const float*)d_in[1];
    if (n_in >= 2 && in_sizes[0] > in_sizes[1]) {   // defensive order check
        const float* tmp = X; X = W; W = tmp;
    }
    float* out = (float*)d_out;

    k_u_prefix<<<dim3(CI / K1_IBLK, 2), 256>>>(X, W);
    k_s0_reduce<<<512, 256>>>();
    k_squash<<<64, 512>>>(nullptr);                 // v0, zero g_s
    k_route<<<dim3(RT_NIB, BB), 256>>>(1);
    k_squash<<<64, 512>>>(nullptr);                 // v1, zero g_s
    k_route<<<dim3(RT_NIB, BB), 256>>>(2);
    k_squash<<<64, 512>>>(out);                     // v2 -> output, zero g_s
    (void)out_size;
}